// round 1
// baseline (speedup 1.0000x reference)
#include <cuda_runtime.h>
#include <cstdint>

#define H 1024
#define B 32
#define S 2048
#define M_TOTAL (B*S)

// ---- scratch (device globals: no allocations allowed) ----
__device__ float g_scores[M_TOTAL];   // [b*S + s]
__device__ float g_cbias[B*H];        // [b*H + h]

__device__ __forceinline__ float tanh_fast(float x){
    float y; asm("tanh.approx.f32 %0, %1;" : "=f"(y) : "f"(x)); return y;
}
__device__ __forceinline__ float tf32f(float x){
    unsigned u; asm("cvt.rna.tf32.f32 %0, %1;" : "=r"(u) : "f"(x));
    return __uint_as_float(u);
}

// ============================================================
// Kernel 0: zero scores + attended output region
// ============================================================
__global__ void zero_kernel(float* __restrict__ outAtt){
    int i = blockIdx.x * 256 + threadIdx.x;   // grid 256 -> 65536 threads
    g_scores[i] = 0.f;
    if (i < B*H) outAtt[i] = 0.f;
}

// ============================================================
// Kernel 1: cbias[b,h] = current[b,:] . Wc[h,:] + b_proj[h]
//   Wc[h,d] = W_proj[h*2048 + 1024 + d]
// ============================================================
__global__ void cbias_kernel(const float* __restrict__ current,
                             const float* __restrict__ Wproj,
                             const float* __restrict__ bproj){
    int lane = threadIdx.x & 31, w = threadIdx.x >> 5;
    int h = blockIdx.x * 8 + w;          // grid.x = 128
    int b = blockIdx.y;                  // grid.y = 32
    const float* cr = current + b*H;
    const float* wr = Wproj + (size_t)h*2048 + H;
    float p = 0.f;
    #pragma unroll 4
    for (int d = lane; d < H; d += 32) p += cr[d]*wr[d];
    #pragma unroll
    for (int o = 16; o; o >>= 1) p += __shfl_xor_sync(0xffffffffu, p, o);
    if (lane == 0) g_cbias[b*H + h] = p + bproj[h];
}

// ============================================================
// Kernel 2: main GEMM (tf32 mma.sync) + fused tanh/score epilogue
//   scores[m] += sum_h tanh(past[m,:].Wp[h,:] + cbias[b,h]) * w_score[h]
//   Wp[h,d] = W_proj[h*2048 + d]
// ============================================================
#define BM 128
#define BN 128
#define BK 32
#define LDSW (BK+4)   // stride 36 -> bank = (4r+c)%32, conflict-free frag loads

__global__ void __launch_bounds__(256) gemm_score_kernel(
    const float* __restrict__ past,
    const float* __restrict__ Wproj,
    const float* __restrict__ wscore)
{
    __shared__ float sA[BM][LDSW];
    __shared__ float sB[BN][LDSW];

    const int tid  = threadIdx.x;
    const int lane = tid & 31, wid = tid >> 5;
    const int warpM = wid & 3;      // 4 warps in M -> 32 rows each
    const int warpN = wid >> 2;     // 2 warps in N -> 64 cols each
    const int mTile = blockIdx.y * BM;
    const int nTile = blockIdx.x * BN;
    const int b = mTile >> 11;      // 2048 rows per batch; BM divides S

    float acc[2][8][4];
    #pragma unroll
    for (int i = 0; i < 2; i++)
        #pragma unroll
        for (int j = 0; j < 8; j++)
            #pragma unroll
            for (int k = 0; k < 4; k++) acc[i][j][k] = 0.f;

    const int ldr = tid >> 3;          // 0..31
    const int ldc = (tid & 7) * 4;     // 0,4,...,28

    for (int k0 = 0; k0 < H; k0 += BK){
        #pragma unroll
        for (int i = 0; i < 4; i++){
            int r = ldr + i*32;
            float4 v = *reinterpret_cast<const float4*>(
                &past[(size_t)(mTile + r)*H + k0 + ldc]);
            sA[r][ldc+0]=tf32f(v.x); sA[r][ldc+1]=tf32f(v.y);
            sA[r][ldc+2]=tf32f(v.z); sA[r][ldc+3]=tf32f(v.w);
            float4 u = *reinterpret_cast<const float4*>(
                &Wproj[(size_t)(nTile + r)*2048 + k0 + ldc]);
            sB[r][ldc+0]=tf32f(u.x); sB[r][ldc+1]=tf32f(u.y);
            sB[r][ldc+2]=tf32f(u.z); sB[r][ldc+3]=tf32f(u.w);
        }
        __syncthreads();

        #pragma unroll
        for (int kk = 0; kk < BK; kk += 8){
            unsigned a[2][4];
            #pragma unroll
            for (int mf = 0; mf < 2; mf++){
                int r = warpM*32 + mf*16 + (lane >> 2);
                int c = kk + (lane & 3);
                a[mf][0] = __float_as_uint(sA[r  ][c  ]);
                a[mf][1] = __float_as_uint(sA[r+8][c  ]);
                a[mf][2] = __float_as_uint(sA[r  ][c+4]);
                a[mf][3] = __float_as_uint(sA[r+8][c+4]);
            }
            #pragma unroll
            for (int nf = 0; nf < 8; nf++){
                int n = warpN*64 + nf*8 + (lane >> 2);
                int c = kk + (lane & 3);
                unsigned b0 = __float_as_uint(sB[n][c  ]);
                unsigned b1 = __float_as_uint(sB[n][c+4]);
                #pragma unroll
                for (int mf = 0; mf < 2; mf++){
                    asm volatile(
                        "mma.sync.aligned.m16n8k8.row.col.f32.tf32.tf32.f32 "
                        "{%0,%1,%2,%3}, {%4,%5,%6,%7}, {%8,%9}, {%0,%1,%2,%3};"
                        : "+f"(acc[mf][nf][0]), "+f"(acc[mf][nf][1]),
                          "+f"(acc[mf][nf][2]), "+f"(acc[mf][nf][3])
                        : "r"(a[mf][0]), "r"(a[mf][1]), "r"(a[mf][2]), "r"(a[mf][3]),
                          "r"(b0), "r"(b1));
                }
            }
        }
        __syncthreads();
    }

    // ---- fused epilogue: tanh + dot(w_score) + per-row partial reduce ----
    float cb[8][2], wv[8][2];
    #pragma unroll
    for (int nf = 0; nf < 8; nf++){
        int h = nTile + warpN*64 + nf*8 + 2*(lane & 3);
        cb[nf][0] = g_cbias[b*H + h];     cb[nf][1] = g_cbias[b*H + h + 1];
        wv[nf][0] = wscore[h];            wv[nf][1] = wscore[h+1];
    }
    #pragma unroll
    for (int mf = 0; mf < 2; mf++){
        #pragma unroll
        for (int rr = 0; rr < 2; rr++){
            float p = 0.f;
            #pragma unroll
            for (int nf = 0; nf < 8; nf++){
                p += tanh_fast(acc[mf][nf][rr*2+0] + cb[nf][0]) * wv[nf][0];
                p += tanh_fast(acc[mf][nf][rr*2+1] + cb[nf][1]) * wv[nf][1];
            }
            // reduce across the 4 lanes of the quad (they hold different cols)
            p += __shfl_xor_sync(0xffffffffu, p, 1);
            p += __shfl_xor_sync(0xffffffffu, p, 2);
            if ((lane & 3) == 0){
                int gRow = mTile + warpM*32 + mf*16 + (lane >> 2) + rr*8;
                atomicAdd(&g_scores[gRow], p);
            }
        }
    }
}

// ============================================================
// Kernel 3: per-batch softmax over S; writes attn_weights to d_out
// ============================================================
__global__ void softmax_kernel(float* __restrict__ attn){
    __shared__ float red[256];
    int bidx = blockIdx.x, tid = threadIdx.x;
    const float* sc = g_scores + bidx*S;
    float m = -1e30f;
    for (int s = tid; s < S; s += 256) m = fmaxf(m, sc[s]);
    red[tid] = m; __syncthreads();
    for (int o = 128; o; o >>= 1){ if (tid < o) red[tid] = fmaxf(red[tid], red[tid+o]); __syncthreads(); }
    m = red[0]; __syncthreads();
    float sum = 0.f;
    float* a = attn + bidx*S;
    for (int s = tid; s < S; s += 256){ float e = __expf(sc[s] - m); a[s] = e; sum += e; }
    red[tid] = sum; __syncthreads();
    for (int o = 128; o; o >>= 1){ if (tid < o) red[tid] += red[tid+o]; __syncthreads(); }
    float inv = 1.f / red[0];
    for (int s = tid; s < S; s += 256) a[s] *= inv;
}

// ============================================================
// Kernel 4: attended[b,d] = sum_s attn[b,s] * past[b,s,d]
// ============================================================
__global__ void attend_kernel(const float* __restrict__ past,
                              const float* __restrict__ attn,
                              float* __restrict__ outAtt){
    __shared__ float w[256];
    int bidx = blockIdx.y, ch = blockIdx.x, tid = threadIdx.x;
    int s0 = ch * 256;
    w[tid] = attn[bidx*S + s0 + tid];
    __syncthreads();
    const float4* P = reinterpret_cast<const float4*>(past + (size_t)(bidx*S + s0)*H);
    float4 acc = make_float4(0.f, 0.f, 0.f, 0.f);
    #pragma unroll 4
    for (int s = 0; s < 256; s++){
        float4 v = P[(size_t)s*256 + tid];
        float ws = w[s];
        acc.x += ws*v.x; acc.y += ws*v.y; acc.z += ws*v.z; acc.w += ws*v.w;
    }
    float* o = outAtt + bidx*H + tid*4;
    atomicAdd(o+0, acc.x); atomicAdd(o+1, acc.y);
    atomicAdd(o+2, acc.z); atomicAdd(o+3, acc.w);
}

// ============================================================
extern "C" void kernel_launch(void* const* d_in, const int* in_sizes, int n_in,
                              void* d_out, int out_size)
{
    const float* current = (const float*)d_in[0];   // [32,1024]
    const float* past    = (const float*)d_in[1];   // [32,2048,1024]
    const float* Wproj   = (const float*)d_in[2];   // [1024,2048]
    const float* bproj   = (const float*)d_in[3];   // [1024]
    const float* wscore  = (const float*)d_in[4];   // [1024]

    float* outAtt  = (float*)d_out;                 // attended [32,1024]
    float* outAttn = (float*)d_out + B*H;           // attn_weights [32,2048]

    zero_kernel   <<<256, 256>>>(outAtt);
    cbias_kernel  <<<dim3(128, 32), 256>>>(current, Wproj, bproj);
    gemm_score_kernel<<<dim3(H/BN, M_TOTAL/BM), 256>>>(past, Wproj, wscore);
    softmax_kernel<<<32, 256>>>(outAttn);
    attend_kernel <<<dim3(S/256, B), 256>>>(past, outAttn, outAtt);
}

// round 3
// speedup vs baseline: 1.8167x; 1.8167x over previous
#include <cuda_runtime.h>
#include <cstdint>

#define H 1024
#define B 32
#define S 2048
#define M_TOTAL (B*S)

// GEMM tiling
#define BM 128
#define BN 256
#define BK 32
#define KS 32                 // K stages = H/BK
#define MT (M_TOTAL/BM)       // 512 m-tiles
#define NT (H/BN)             // 4 n-tiles
#define PADW 36               // padded row stride in floats (conflict-free)
#define A_BLK_FLOATS (BM*PADW)          // 4608  (18432 B)
#define B_BLK_FLOATS (BN*PADW)          // 9216  (36864 B)
#define A_BLK_BYTES  (A_BLK_FLOATS*4)
#define B_BLK_BYTES  (B_BLK_FLOATS*4)
#define STAGE_BYTES  (A_BLK_BYTES + B_BLK_BYTES)   // 55296
#define STAGE_FLOATS (STAGE_BYTES/4)
#define NSTAGES 3
#define DSMEM_BYTES (NSTAGES*STAGE_BYTES)          // 165888

// ---------------- device-global scratch ----------------
__device__ float g_scores[M_TOTAL];
__device__ float g_cbias[B*H];
__device__ float g_Astg[(size_t)MT*KS*A_BLK_FLOATS];   // ~302 MB staged A
__device__ float g_Bstg[(size_t)NT*KS*B_BLK_FLOATS];   // ~4.7 MB staged B

// ---------------- helpers ----------------
__device__ __forceinline__ float tanh_fast(float x){
    float y; asm("tanh.approx.f32 %0, %1;" : "=f"(y) : "f"(x)); return y;
}
__device__ __forceinline__ uint32_t smem_u32(const void* p){
    uint32_t a;
    asm("{ .reg .u64 t; cvta.to.shared.u64 t, %1; cvt.u32.u64 %0, t; }" : "=r"(a) : "l"(p));
    return a;
}
#define MBARRIER_INIT(addr, cnt) \
    asm volatile("mbarrier.init.shared.b64 [%0], %1;" :: "r"((uint32_t)(addr)), "r"((uint32_t)(cnt)) : "memory")
#define MBARRIER_EXPECT_TX(addr, tx) \
    asm volatile("mbarrier.arrive.expect_tx.shared.b64 _, [%0], %1;" \
                 :: "r"((uint32_t)(addr)), "r"((uint32_t)(tx)) : "memory")
#define MBARRIER_WAIT_PARITY(addr, ph) do { \
    uint32_t _m = (uint32_t)(addr), _p = (uint32_t)(ph), _d; \
    asm volatile("{\n\t.reg .pred p;\n\t" \
        "mbarrier.try_wait.parity.acquire.cta.shared::cta.b64 p, [%1], %2;\n\t" \
        "selp.b32 %0, 1, 0, p;\n\t}" : "=r"(_d) : "r"(_m), "r"(_p) : "memory"); \
    if (!_d) { \
        asm volatile("{\n\t.reg .pred P1;\n\t" \
            "WL_%=:\n\t" \
            "mbarrier.try_wait.parity.acquire.cta.shared::cta.b64 P1, [%0], %1, 0x989680;\n\t" \
            "@P1 bra.uni WD_%=;\n\t" \
            "bra.uni WL_%=;\n\t" \
            "WD_%=:\n\t}" :: "r"(_m), "r"(_p) : "memory"); \
    } \
} while(0)

__device__ __forceinline__ void bulk_g2s(uint32_t dst, const void* src,
                                         uint32_t bytes, uint32_t mbar){
    asm volatile(
        "cp.async.bulk.shared::cluster.global.mbarrier::complete_tx::bytes "
        "[%0], [%1], %2, [%3];"
        :: "r"(dst), "l"(src), "r"(bytes), "r"(mbar) : "memory");
}

// ============================================================
// Kernel 0: zero scores + attended region
// ============================================================
__global__ void zero_kernel(float* __restrict__ outAtt){
    int i = blockIdx.x * 256 + threadIdx.x;
    g_scores[i] = 0.f;
    if (i < B*H) outAtt[i] = 0.f;
}

// ============================================================
// Staging: past -> tile-contiguous smem images (padded stride 36)
// block covers (mtile, kstage, 32-row group); 256 threads
// ============================================================
__global__ void stageA_kernel(const float* __restrict__ past){
    int bid = blockIdx.x;
    int mg = bid & 3;
    int ks = (bid >> 2) & 31;
    int mt = bid >> 7;
    int tid = threadIdx.x;
    int mloc = mg*32 + (tid >> 3);
    int k = (tid & 7) * 4;
    float4 v = *reinterpret_cast<const float4*>(
        &past[((size_t)(mt*BM + mloc))*H + ks*BK + k]);
    *reinterpret_cast<float4*>(
        &g_Astg[((size_t)(mt*KS + ks)*BM + mloc)*PADW + k]) = v;
}

__global__ void stageB_kernel(const float* __restrict__ Wproj){
    int bid = blockIdx.x;
    int ng = bid & 7;
    int ks = (bid >> 3) & 31;
    int nt = bid >> 8;
    int tid = threadIdx.x;
    int nloc = ng*32 + (tid >> 3);
    int k = (tid & 7) * 4;
    float4 v = *reinterpret_cast<const float4*>(
        &Wproj[((size_t)(nt*BN + nloc))*2048 + ks*BK + k]);
    *reinterpret_cast<float4*>(
        &g_Bstg[((size_t)(nt*KS + ks)*BN + nloc)*PADW + k]) = v;
}

// ============================================================
// Kernel 1: cbias[b,h] = current[b,:] . Wc[h,:] + b_proj[h]
// ============================================================
__global__ void cbias_kernel(const float* __restrict__ current,
                             const float* __restrict__ Wproj,
                             const float* __restrict__ bproj){
    int lane = threadIdx.x & 31, w = threadIdx.x >> 5;
    int h = blockIdx.x * 8 + w;
    int b = blockIdx.y;
    const float* cr = current + b*H;
    const float* wr = Wproj + (size_t)h*2048 + H;
    float p = 0.f;
    #pragma unroll 4
    for (int d = lane; d < H; d += 32) p += cr[d]*wr[d];
    #pragma unroll
    for (int o = 16; o; o >>= 1) p += __shfl_xor_sync(0xffffffffu, p, o);
    if (lane == 0) g_cbias[b*H + h] = p + bproj[h];
}

// ============================================================
// Kernel 2: bulk-copy-fed mma.sync tf32 GEMM + fused tanh/score epilogue
//   CTA tile 128(M) x 256(N), 8 warps of 64x64
// ============================================================
__global__ void __launch_bounds__(256, 1) gemm_score(
    const float* __restrict__ wscore)
{
    extern __shared__ float dsm[];
    __shared__ uint64_t mbar[NSTAGES];
    __shared__ float cbS[BN];
    __shared__ float wsS[BN];

    const int tid = threadIdx.x, wid = tid >> 5, lane = tid & 31;
    const int ntIdx = blockIdx.x, mtIdx = blockIdx.y;
    const int mTile = mtIdx * BM;
    const int nTile = ntIdx * BN;
    const int b = mTile >> 11;
    const uint32_t smemBase = smem_u32(dsm);

    if (tid == 0){
        #pragma unroll
        for (int s = 0; s < NSTAGES; s++) MBARRIER_INIT(smem_u32(&mbar[s]), 1);
    }
    cbS[tid] = g_cbias[b*H + nTile + tid];
    wsS[tid] = wscore[nTile + tid];
    __syncthreads();

    // prologue: fill pipeline
    if (tid == 0){
        #pragma unroll
        for (int s = 0; s < NSTAGES; s++){
            uint32_t mb = smem_u32(&mbar[s]);
            MBARRIER_EXPECT_TX(mb, STAGE_BYTES);
            bulk_g2s(smemBase + s*STAGE_BYTES,
                     &g_Astg[((size_t)(mtIdx*KS + s))*A_BLK_FLOATS],
                     A_BLK_BYTES, mb);
            bulk_g2s(smemBase + s*STAGE_BYTES + A_BLK_BYTES,
                     &g_Bstg[((size_t)(ntIdx*KS + s))*B_BLK_FLOATS],
                     B_BLK_BYTES, mb);
        }
    }

    const int warpM = wid >> 2;          // 0..1 (64 rows each)
    const int warpN = wid & 3;           // 0..3 (64 cols each)
    const int qr = lane >> 2;            // quad row 0..7
    const int qc = lane & 3;             // quad col 0..3

    float acc[4][8][4];
    #pragma unroll
    for (int i = 0; i < 4; i++)
        #pragma unroll
        for (int j = 0; j < 8; j++)
            #pragma unroll
            for (int k = 0; k < 4; k++) acc[i][j][k] = 0.f;

    for (int s = 0; s < KS; s++){
        int slot = s % NSTAGES;
        MBARRIER_WAIT_PARITY(smem_u32(&mbar[slot]), (s/NSTAGES)&1);

        const float* sA = dsm + slot*STAGE_FLOATS;
        const float* sB = sA + A_BLK_FLOATS;

        #pragma unroll
        for (int kk = 0; kk < BK; kk += 8){
            const int c = kk + qc;
            unsigned a[4][4];
            #pragma unroll
            for (int mf = 0; mf < 4; mf++){
                int base = (warpM*64 + mf*16 + qr)*PADW + c;
                a[mf][0] = __float_as_uint(sA[base]);
                a[mf][1] = __float_as_uint(sA[base + 8*PADW]);
                a[mf][2] = __float_as_uint(sA[base + 4]);
                a[mf][3] = __float_as_uint(sA[base + 8*PADW + 4]);
            }
            #pragma unroll
            for (int nf = 0; nf < 8; nf++){
                int bidx = (warpN*64 + nf*8 + qr)*PADW + c;
                unsigned b0 = __float_as_uint(sB[bidx]);
                unsigned b1 = __float_as_uint(sB[bidx + 4]);
                #pragma unroll
                for (int mf = 0; mf < 4; mf++){
                    asm volatile(
                        "mma.sync.aligned.m16n8k8.row.col.f32.tf32.tf32.f32 "
                        "{%0,%1,%2,%3}, {%4,%5,%6,%7}, {%8,%9}, {%0,%1,%2,%3};"
                        : "+f"(acc[mf][nf][0]), "+f"(acc[mf][nf][1]),
                          "+f"(acc[mf][nf][2]), "+f"(acc[mf][nf][3])
                        : "r"(a[mf][0]), "r"(a[mf][1]), "r"(a[mf][2]), "r"(a[mf][3]),
                          "r"(b0), "r"(b1));
                }
            }
        }
        __syncthreads();   // all warps done reading this slot
        if (tid == 0 && s + NSTAGES < KS){
            int ns = s + NSTAGES;
            uint32_t mb = smem_u32(&mbar[slot]);
            MBARRIER_EXPECT_TX(mb, STAGE_BYTES);
            bulk_g2s(smemBase + slot*STAGE_BYTES,
                     &g_Astg[((size_t)(mtIdx*KS + ns))*A_BLK_FLOATS],
                     A_BLK_BYTES, mb);
            bulk_g2s(smemBase + slot*STAGE_BYTES + A_BLK_BYTES,
                     &g_Bstg[((size_t)(ntIdx*KS + ns))*B_BLK_FLOATS],
                     B_BLK_BYTES, mb);
        }
    }

    // ---- fused epilogue: tanh + dot(w_score) per row, quad-reduce ----
    #pragma unroll
    for (int mf = 0; mf < 4; mf++){
        #pragma unroll
        for (int rr = 0; rr < 2; rr++){
            float p = 0.f;
            #pragma unroll
            for (int nf = 0; nf < 8; nf++){
                int c0 = warpN*64 + nf*8 + qc*2;
                p += tanh_fast(acc[mf][nf][rr*2+0] + cbS[c0    ]) * wsS[c0    ];
                p += tanh_fast(acc[mf][nf][rr*2+1] + cbS[c0 + 1]) * wsS[c0 + 1];
            }
            p += __shfl_xor_sync(0xffffffffu, p, 1);
            p += __shfl_xor_sync(0xffffffffu, p, 2);
            if (qc == 0){
                int r = mTile + warpM*64 + mf*16 + qr + rr*8;
                atomicAdd(&g_scores[r], p);
            }
        }
    }
}

// ============================================================
// Kernel 3: per-batch softmax over S
// ============================================================
__global__ void softmax_kernel(float* __restrict__ attn){
    __shared__ float red[256];
    int bidx = blockIdx.x, tid = threadIdx.x;
    const float* sc = g_scores + bidx*S;
    float m = -1e30f;
    for (int s = tid; s < S; s += 256) m = fmaxf(m, sc[s]);
    red[tid] = m; __syncthreads();
    for (int o = 128; o; o >>= 1){ if (tid < o) red[tid] = fmaxf(red[tid], red[tid+o]); __syncthreads(); }
    m = red[0]; __syncthreads();
    float sum = 0.f;
    float* a = attn + bidx*S;
    for (int s = tid; s < S; s += 256){ float e = __expf(sc[s] - m); a[s] = e; sum += e; }
    red[tid] = sum; __syncthreads();
    for (int o = 128; o; o >>= 1){ if (tid < o) red[tid] += red[tid+o]; __syncthreads(); }
    float inv = 1.f / red[0];
    for (int s = tid; s < S; s += 256) a[s] *= inv;
}

// ============================================================
// Kernel 4: attended[b,d] = sum_s attn[b,s] * past[b,s,d]
// ============================================================
__global__ void attend_kernel(const float* __restrict__ past,
                              const float* __restrict__ attn,
                              float* __restrict__ outAtt){
    __shared__ float w[256];
    int bidx = blockIdx.y, ch = blockIdx.x, tid = threadIdx.x;
    int s0 = ch * 256;
    w[tid] = attn[bidx*S + s0 + tid];
    __syncthreads();
    const float4* P = reinterpret_cast<const float4*>(past + (size_t)(bidx*S + s0)*H);
    float4 acc = make_float4(0.f, 0.f, 0.f, 0.f);
    #pragma unroll 4
    for (int s = 0; s < 256; s++){
        float4 v = P[(size_t)s*256 + tid];
        float ws = w[s];
        acc.x += ws*v.x; acc.y += ws*v.y; acc.z += ws*v.z; acc.w += ws*v.w;
    }
    float* o = outAtt + bidx*H + tid*4;
    atomicAdd(o+0, acc.x); atomicAdd(o+1, acc.y);
    atomicAdd(o+2, acc.z); atomicAdd(o+3, acc.w);
}

// ============================================================
extern "C" void kernel_launch(void* const* d_in, const int* in_sizes, int n_in,
                              void* d_out, int out_size)
{
    const float* current = (const float*)d_in[0];   // [32,1024]
    const float* past    = (const float*)d_in[1];   // [32,2048,1024]
    const float* Wproj   = (const float*)d_in[2];   // [1024,2048]
    const float* bproj   = (const float*)d_in[3];   // [1024]
    const float* wscore  = (const float*)d_in[4];   // [1024]

    float* outAtt  = (float*)d_out;                 // attended [32,1024]
    float* outAttn = (float*)d_out + B*H;           // attn_weights [32,2048]

    static int smem_set = 0;
    if (!smem_set){
        cudaFuncSetAttribute(gemm_score,
                             cudaFuncAttributeMaxDynamicSharedMemorySize, DSMEM_BYTES);
        smem_set = 1;
    }

    zero_kernel   <<<256, 256>>>(outAtt);
    stageA_kernel <<<MT*KS*4, 256>>>(past);      // 65536 blocks
    stageB_kernel <<<NT*KS*8, 256>>>(Wproj);     // 1024 blocks
    cbias_kernel  <<<dim3(128, 32), 256>>>(current, Wproj, bproj);
    gemm_score    <<<dim3(NT, MT), 256, DSMEM_BYTES>>>(wscore);
    softmax_kernel<<<32, 256>>>(outAttn);
    attend_kernel <<<dim3(S/256, B), 256>>>(past, outAttn, outAtt);
}

// round 4
// speedup vs baseline: 2.9910x; 1.6464x over previous
#include <cuda_runtime.h>
#include <cuda_fp16.h>
#include <cstdint>

#define H 1024
#define B 32
#define S 2048
#define M_TOTAL (B*S)

// GEMM tiling (fp16 operands, fp32 accum)
#define BM 128
#define BN 256
#define BK 64                 // K elements per stage
#define KS2 16                // stages = H/BK
#define MT (M_TOTAL/BM)       // 512
#define NT (H/BN)             // 4
#define PADW 72               // padded row stride in halves (conflict-free)
#define A_BLK_HALFS (BM*PADW)           // 9216  -> 18432 B
#define B_BLK_HALFS (BN*PADW)           // 18432 -> 36864 B
#define A_BLK_BYTES (A_BLK_HALFS*2)
#define B_BLK_BYTES (B_BLK_HALFS*2)
#define STAGE_BYTES (A_BLK_BYTES + B_BLK_BYTES)   // 55296
#define NSTAGES 3
#define DSMEM_BYTES (NSTAGES*STAGE_BYTES)         // 165888

// ---------------- device-global scratch ----------------
__device__ float g_scores[M_TOTAL];
__device__ float g_cbias[B*H];
__device__ __align__(128) __half g_Ah[(size_t)MT*KS2*A_BLK_HALFS];  // ~151 MB
__device__ __align__(128) __half g_Bh[(size_t)NT*KS2*B_BLK_HALFS];  // ~2.4 MB

// ---------------- helpers ----------------
__device__ __forceinline__ float tanh_fast(float x){
    float y; asm("tanh.approx.f32 %0, %1;" : "=f"(y) : "f"(x)); return y;
}
__device__ __forceinline__ uint32_t smem_u32(const void* p){
    uint32_t a;
    asm("{ .reg .u64 t; cvta.to.shared.u64 t, %1; cvt.u32.u64 %0, t; }" : "=r"(a) : "l"(p));
    return a;
}
#define MBARRIER_INIT(addr, cnt) \
    asm volatile("mbarrier.init.shared.b64 [%0], %1;" :: "r"((uint32_t)(addr)), "r"((uint32_t)(cnt)) : "memory")
#define MBARRIER_EXPECT_TX(addr, tx) \
    asm volatile("mbarrier.arrive.expect_tx.shared.b64 _, [%0], %1;" \
                 :: "r"((uint32_t)(addr)), "r"((uint32_t)(tx)) : "memory")
#define MBARRIER_WAIT_PARITY(addr, ph) do { \
    uint32_t _m = (uint32_t)(addr), _p = (uint32_t)(ph), _d; \
    asm volatile("{\n\t.reg .pred p;\n\t" \
        "mbarrier.try_wait.parity.acquire.cta.shared::cta.b64 p, [%1], %2;\n\t" \
        "selp.b32 %0, 1, 0, p;\n\t}" : "=r"(_d) : "r"(_m), "r"(_p) : "memory"); \
    if (!_d) { \
        asm volatile("{\n\t.reg .pred P1;\n\t" \
            "WL_%=:\n\t" \
            "mbarrier.try_wait.parity.acquire.cta.shared::cta.b64 P1, [%0], %1, 0x989680;\n\t" \
            "@P1 bra.uni WD_%=;\n\t" \
            "bra.uni WL_%=;\n\t" \
            "WD_%=:\n\t}" :: "r"(_m), "r"(_p) : "memory"); \
    } \
} while(0)

__device__ __forceinline__ void bulk_g2s(uint32_t dst, const void* src,
                                         uint32_t bytes, uint32_t mbar){
    asm volatile(
        "cp.async.bulk.shared::cluster.global.mbarrier::complete_tx::bytes "
        "[%0], [%1], %2, [%3];"
        :: "r"(dst), "l"(src), "r"(bytes), "r"(mbar) : "memory");
}
__device__ __forceinline__ void ldmx4(uint32_t* r, uint32_t addr){
    asm volatile("ldmatrix.sync.aligned.m8n8.x4.shared.b16 {%0,%1,%2,%3}, [%4];"
        : "=r"(r[0]), "=r"(r[1]), "=r"(r[2]), "=r"(r[3]) : "r"(addr));
}
__device__ __forceinline__ void mma16816(float* d, const uint32_t* a,
                                         uint32_t b0, uint32_t b1){
    asm volatile(
        "mma.sync.aligned.m16n8k16.row.col.f32.f16.f16.f32 "
        "{%0,%1,%2,%3}, {%4,%5,%6,%7}, {%8,%9}, {%0,%1,%2,%3};"
        : "+f"(d[0]), "+f"(d[1]), "+f"(d[2]), "+f"(d[3])
        : "r"(a[0]), "r"(a[1]), "r"(a[2]), "r"(a[3]), "r"(b0), "r"(b1));
}

// ============================================================
// Kernel 0: zero scores + attended region
// ============================================================
__global__ void zero_kernel(float* __restrict__ outAtt){
    int i = blockIdx.x * 256 + threadIdx.x;
    g_scores[i] = 0.f;
    if (i < B*H) outAtt[i] = 0.f;
}

// ============================================================
// Staging: fp32 -> fp16 tile-contiguous images (padded stride 72 halves)
// ============================================================
__global__ void stageA_kernel(const float* __restrict__ past){
    int bidx = blockIdx.x;               // MT*KS2 = 8192 blocks
    int ks = bidx & 15;
    int mt = bidx >> 4;
    int t = threadIdx.x;                 // 256
    int row = t >> 1;
    int off = (t & 1) * 32;
    const float4* src = reinterpret_cast<const float4*>(
        &past[(size_t)(mt*BM + row)*H + ks*BK + off]);
    __half hbuf[32];
    #pragma unroll
    for (int i = 0; i < 8; i++){
        float4 v = src[i];
        hbuf[i*4+0] = __float2half_rn(v.x); hbuf[i*4+1] = __float2half_rn(v.y);
        hbuf[i*4+2] = __float2half_rn(v.z); hbuf[i*4+3] = __float2half_rn(v.w);
    }
    uint4* dst = reinterpret_cast<uint4*>(
        &g_Ah[((size_t)(mt*KS2 + ks)*BM + row)*PADW + off]);
    const uint4* hb = reinterpret_cast<const uint4*>(hbuf);
    #pragma unroll
    for (int j = 0; j < 4; j++) dst[j] = hb[j];
}

__global__ void stageB_kernel(const float* __restrict__ Wproj){
    int bidx = blockIdx.x;               // NT*KS2 = 64 blocks, 512 threads
    int ks = bidx & 15;
    int nt = bidx >> 4;
    int t = threadIdx.x;
    int row = t >> 1;                    // 0..255
    int off = (t & 1) * 32;
    const float4* src = reinterpret_cast<const float4*>(
        &Wproj[(size_t)(nt*BN + row)*2048 + ks*BK + off]);
    __half hbuf[32];
    #pragma unroll
    for (int i = 0; i < 8; i++){
        float4 v = src[i];
        hbuf[i*4+0] = __float2half_rn(v.x); hbuf[i*4+1] = __float2half_rn(v.y);
        hbuf[i*4+2] = __float2half_rn(v.z); hbuf[i*4+3] = __float2half_rn(v.w);
    }
    uint4* dst = reinterpret_cast<uint4*>(
        &g_Bh[((size_t)(nt*KS2 + ks)*BN + row)*PADW + off]);
    const uint4* hb = reinterpret_cast<const uint4*>(hbuf);
    #pragma unroll
    for (int j = 0; j < 4; j++) dst[j] = hb[j];
}

// ============================================================
// Kernel 1: cbias[b,h] = current[b,:] . Wc[h,:] + b_proj[h]
// ============================================================
__global__ void cbias_kernel(const float* __restrict__ current,
                             const float* __restrict__ Wproj,
                             const float* __restrict__ bproj){
    int lane = threadIdx.x & 31, w = threadIdx.x >> 5;
    int h = blockIdx.x * 8 + w;
    int b = blockIdx.y;
    const float4* cr = reinterpret_cast<const float4*>(current + b*H);
    const float4* wr = reinterpret_cast<const float4*>(Wproj + (size_t)h*2048 + H);
    float p = 0.f;
    #pragma unroll
    for (int d = lane; d < 256; d += 32){
        float4 c = cr[d], v = wr[d];
        p += c.x*v.x + c.y*v.y + c.z*v.z + c.w*v.w;
    }
    #pragma unroll
    for (int o = 16; o; o >>= 1) p += __shfl_xor_sync(0xffffffffu, p, o);
    if (lane == 0) g_cbias[b*H + h] = p + bproj[h];
}

// ============================================================
// Kernel 2: fp16 mma.sync GEMM (ldmatrix + bulk-copy pipeline)
//           + fused tanh/score epilogue
// ============================================================
__global__ void __launch_bounds__(256, 1) gemm_score(
    const float* __restrict__ wscore)
{
    extern __shared__ __align__(128) char dsm[];
    __shared__ uint64_t mbar[NSTAGES];
    __shared__ float cbS[BN];
    __shared__ float wsS[BN];

    const int tid = threadIdx.x, wid = tid >> 5, lane = tid & 31;
    const int ntIdx = blockIdx.x, mtIdx = blockIdx.y;
    const int mTile = mtIdx * BM;
    const int nTile = ntIdx * BN;
    const int b = mTile >> 11;
    const uint32_t smemBase = smem_u32(dsm);

    if (tid == 0){
        #pragma unroll
        for (int s = 0; s < NSTAGES; s++) MBARRIER_INIT(smem_u32(&mbar[s]), 1);
    }
    cbS[tid] = g_cbias[b*H + nTile + tid];
    wsS[tid] = wscore[nTile + tid];
    __syncthreads();

    if (tid == 0){
        #pragma unroll
        for (int s = 0; s < NSTAGES; s++){
            uint32_t mb = smem_u32(&mbar[s]);
            MBARRIER_EXPECT_TX(mb, STAGE_BYTES);
            bulk_g2s(smemBase + s*STAGE_BYTES,
                     &g_Ah[((size_t)(mtIdx*KS2 + s))*A_BLK_HALFS], A_BLK_BYTES, mb);
            bulk_g2s(smemBase + s*STAGE_BYTES + A_BLK_BYTES,
                     &g_Bh[((size_t)(ntIdx*KS2 + s))*B_BLK_HALFS], B_BLK_BYTES, mb);
        }
    }

    const int warpM = wid >> 2;           // 0..1 (64 rows)
    const int warpN = wid & 3;            // 0..3 (64 cols)
    const int qr = lane >> 2, qc = lane & 3;

    // per-lane ldmatrix base offsets (in halves)
    const int aLane = (warpM*64 + (lane & 15))*PADW + (lane >> 4)*8;
    const int bLane = (warpN*64 + ((lane >> 4) << 3) + (lane & 7))*PADW
                      + ((lane >> 3) & 1)*8;

    float acc[4][8][4];
    #pragma unroll
    for (int i = 0; i < 4; i++)
        #pragma unroll
        for (int j = 0; j < 8; j++)
            #pragma unroll
            for (int k = 0; k < 4; k++) acc[i][j][k] = 0.f;

    for (int s = 0; s < KS2; s++){
        int slot = s % NSTAGES;
        MBARRIER_WAIT_PARITY(smem_u32(&mbar[slot]), (s/NSTAGES)&1);

        uint32_t aBase = smemBase + slot*STAGE_BYTES;
        uint32_t bBase = aBase + A_BLK_BYTES;

        #pragma unroll
        for (int kk = 0; kk < BK; kk += 16){
            uint32_t a[4][4], bq[4][4];
            #pragma unroll
            for (int mf = 0; mf < 4; mf++)
                ldmx4(a[mf], aBase + (uint32_t)(aLane + mf*16*PADW + kk)*2);
            #pragma unroll
            for (int np = 0; np < 4; np++)
                ldmx4(bq[np], bBase + (uint32_t)(bLane + np*16*PADW + kk)*2);
            #pragma unroll
            for (int np = 0; np < 4; np++){
                #pragma unroll
                for (int hh = 0; hh < 2; hh++){
                    int nf = np*2 + hh;
                    #pragma unroll
                    for (int mf = 0; mf < 4; mf++)
                        mma16816(acc[mf][nf], a[mf], bq[np][hh*2], bq[np][hh*2+1]);
                }
            }
        }
        __syncthreads();
        if (tid == 0 && s + NSTAGES < KS2){
            int ns = s + NSTAGES;
            uint32_t mb = smem_u32(&mbar[slot]);
            MBARRIER_EXPECT_TX(mb, STAGE_BYTES);
            bulk_g2s(smemBase + slot*STAGE_BYTES,
                     &g_Ah[((size_t)(mtIdx*KS2 + ns))*A_BLK_HALFS], A_BLK_BYTES, mb);
            bulk_g2s(smemBase + slot*STAGE_BYTES + A_BLK_BYTES,
                     &g_Bh[((size_t)(ntIdx*KS2 + ns))*B_BLK_HALFS], B_BLK_BYTES, mb);
        }
    }

    // ---- fused epilogue: tanh + dot(w_score) per row, quad-reduce ----
    #pragma unroll
    for (int mf = 0; mf < 4; mf++){
        #pragma unroll
        for (int rr = 0; rr < 2; rr++){
            float p = 0.f;
            #pragma unroll
            for (int nf = 0; nf < 8; nf++){
                int c0 = warpN*64 + nf*8 + qc*2;
                p += tanh_fast(acc[mf][nf][rr*2+0] + cbS[c0    ]) * wsS[c0    ];
                p += tanh_fast(acc[mf][nf][rr*2+1] + cbS[c0 + 1]) * wsS[c0 + 1];
            }
            p += __shfl_xor_sync(0xffffffffu, p, 1);
            p += __shfl_xor_sync(0xffffffffu, p, 2);
            if (qc == 0){
                int r = mTile + warpM*64 + mf*16 + qr + rr*8;
                atomicAdd(&g_scores[r], p);
            }
        }
    }
}

// ============================================================
// Kernel 3: per-batch softmax over S
// ============================================================
__global__ void softmax_kernel(float* __restrict__ attn){
    __shared__ float red[256];
    int bidx = blockIdx.x, tid = threadIdx.x;
    const float* sc = g_scores + bidx*S;
    float m = -1e30f;
    for (int s = tid; s < S; s += 256) m = fmaxf(m, sc[s]);
    red[tid] = m; __syncthreads();
    for (int o = 128; o; o >>= 1){ if (tid < o) red[tid] = fmaxf(red[tid], red[tid+o]); __syncthreads(); }
    m = red[0]; __syncthreads();
    float sum = 0.f;
    float* a = attn + bidx*S;
    for (int s = tid; s < S; s += 256){ float e = __expf(sc[s] - m); a[s] = e; sum += e; }
    red[tid] = sum; __syncthreads();
    for (int o = 128; o; o >>= 1){ if (tid < o) red[tid] += red[tid+o]; __syncthreads(); }
    float inv = 1.f / red[0];
    for (int s = tid; s < S; s += 256) a[s] *= inv;
}

// ============================================================
// Kernel 4: attended[b,d] = sum_s attn[b,s] * past[b,s,d]
// ============================================================
__global__ void attend_kernel(const float* __restrict__ past,
                              const float* __restrict__ attn,
                              float* __restrict__ outAtt){
    __shared__ float w[256];
    int bidx = blockIdx.y, ch = blockIdx.x, tid = threadIdx.x;
    int s0 = ch * 256;
    w[tid] = attn[bidx*S + s0 + tid];
    __syncthreads();
    const float4* P = reinterpret_cast<const float4*>(past + (size_t)(bidx*S + s0)*H);
    float4 acc = make_float4(0.f, 0.f, 0.f, 0.f);
    #pragma unroll 4
    for (int s = 0; s < 256; s++){
        float4 v = P[(size_t)s*256 + tid];
        float ws = w[s];
        acc.x += ws*v.x; acc.y += ws*v.y; acc.z += ws*v.z; acc.w += ws*v.w;
    }
    float* o = outAtt + bidx*H + tid*4;
    atomicAdd(o+0, acc.x); atomicAdd(o+1, acc.y);
    atomicAdd(o+2, acc.z); atomicAdd(o+3, acc.w);
}

// ============================================================
extern "C" void kernel_launch(void* const* d_in, const int* in_sizes, int n_in,
                              void* d_out, int out_size)
{
    const float* current = (const float*)d_in[0];   // [32,1024]
    const float* past    = (const float*)d_in[1];   // [32,2048,1024]
    const float* Wproj   = (const float*)d_in[2];   // [1024,2048]
    const float* bproj   = (const float*)d_in[3];   // [1024]
    const float* wscore  = (const float*)d_in[4];   // [1024]

    float* outAtt  = (float*)d_out;                 // attended [32,1024]
    float* outAttn = (float*)d_out + B*H;           // attn_weights [32,2048]

    static int smem_set = 0;
    if (!smem_set){
        cudaFuncSetAttribute(gemm_score,
                             cudaFuncAttributeMaxDynamicSharedMemorySize, DSMEM_BYTES);
        smem_set = 1;
    }

    zero_kernel   <<<256, 256>>>(outAtt);
    stageA_kernel <<<MT*KS2, 256>>>(past);       // 8192 blocks
    stageB_kernel <<<NT*KS2, 512>>>(Wproj);      // 64 blocks
    cbias_kernel  <<<dim3(128, 32), 256>>>(current, Wproj, bproj);
    gemm_score    <<<dim3(NT, MT), 256, DSMEM_BYTES>>>(wscore);
    softmax_kernel<<<32, 256>>>(outAttn);
    attend_kernel <<<dim3(S/256, B), 256>>>(past, outAttn, outAtt);
}

// round 5
// speedup vs baseline: 3.1230x; 1.0441x over previous
#include <cuda_runtime.h>
#include <cuda_fp16.h>
#include <cstdint>

#define H 1024
#define B 32
#define S 2048
#define M_TOTAL (B*S)

// GEMM tiling (fp16 operands, fp32 accum), swizzled SW128 images
#define BM 128
#define BN 256
#define BK 64                  // K halves per stage = 128B row
#define KS2 16                 // stages = H/BK
#define MT (M_TOTAL/BM)        // 512
#define NT (H/BN)              // 4
#define A_TILE_HALFS (BM*BK)   // 8192  -> 16384 B
#define B_TILE_HALFS (BN*BK)   // 16384 -> 32768 B
#define A_TILE_BYTES (A_TILE_HALFS*2)
#define B_TILE_BYTES (B_TILE_HALFS*2)
#define STAGE_BYTES  (A_TILE_BYTES + B_TILE_BYTES)   // 49152
#define NSTAGES 4
#define DSMEM_BYTES (NSTAGES*STAGE_BYTES)            // 196608

#define SW128(off) ((off) ^ (((off) >> 3) & 0x70))

// ---------------- device-global scratch ----------------
__device__ float g_scores[M_TOTAL];
__device__ float g_cbias[B*H];
__device__ __align__(128) __half g_Ah[(size_t)MT*KS2*A_TILE_HALFS];  // 128 MB
__device__ __align__(128) __half g_Bh[(size_t)NT*KS2*B_TILE_HALFS];  // 2 MB

// ---------------- helpers ----------------
__device__ __forceinline__ float tanh_fast(float x){
    float y; asm("tanh.approx.f32 %0, %1;" : "=f"(y) : "f"(x)); return y;
}
__device__ __forceinline__ uint32_t smem_u32(const void* p){
    uint32_t a;
    asm("{ .reg .u64 t; cvta.to.shared.u64 t, %1; cvt.u32.u64 %0, t; }" : "=r"(a) : "l"(p));
    return a;
}
#define MBARRIER_INIT(addr, cnt) \
    asm volatile("mbarrier.init.shared.b64 [%0], %1;" :: "r"((uint32_t)(addr)), "r"((uint32_t)(cnt)) : "memory")
#define MBARRIER_EXPECT_TX(addr, tx) \
    asm volatile("mbarrier.arrive.expect_tx.shared.b64 _, [%0], %1;" \
                 :: "r"((uint32_t)(addr)), "r"((uint32_t)(tx)) : "memory")
#define MBARRIER_WAIT_PARITY(addr, ph) do { \
    uint32_t _m = (uint32_t)(addr), _p = (uint32_t)(ph), _d; \
    asm volatile("{\n\t.reg .pred p;\n\t" \
        "mbarrier.try_wait.parity.acquire.cta.shared::cta.b64 p, [%1], %2;\n\t" \
        "selp.b32 %0, 1, 0, p;\n\t}" : "=r"(_d) : "r"(_m), "r"(_p) : "memory"); \
    if (!_d) { \
        asm volatile("{\n\t.reg .pred P1;\n\t" \
            "WL_%=:\n\t" \
            "mbarrier.try_wait.parity.acquire.cta.shared::cta.b64 P1, [%0], %1, 0x989680;\n\t" \
            "@P1 bra.uni WD_%=;\n\t" \
            "bra.uni WL_%=;\n\t" \
            "WD_%=:\n\t}" :: "r"(_m), "r"(_p) : "memory"); \
    } \
} while(0)

__device__ __forceinline__ void bulk_g2s(uint32_t dst, const void* src,
                                         uint32_t bytes, uint32_t mbar){
    asm volatile(
        "cp.async.bulk.shared::cluster.global.mbarrier::complete_tx::bytes "
        "[%0], [%1], %2, [%3];"
        :: "r"(dst), "l"(src), "r"(bytes), "r"(mbar) : "memory");
}
__device__ __forceinline__ void ldmx4(uint32_t* r, uint32_t addr){
    asm volatile("ldmatrix.sync.aligned.m8n8.x4.shared.b16 {%0,%1,%2,%3}, [%4];"
        : "=r"(r[0]), "=r"(r[1]), "=r"(r[2]), "=r"(r[3]) : "r"(addr));
}
__device__ __forceinline__ void mma16816(float* d, const uint32_t* a,
                                         uint32_t b0, uint32_t b1){
    asm volatile(
        "mma.sync.aligned.m16n8k16.row.col.f32.f16.f16.f32 "
        "{%0,%1,%2,%3}, {%4,%5,%6,%7}, {%8,%9}, {%0,%1,%2,%3};"
        : "+f"(d[0]), "+f"(d[1]), "+f"(d[2]), "+f"(d[3])
        : "r"(a[0]), "r"(a[1]), "r"(a[2]), "r"(a[3]), "r"(b0), "r"(b1));
}

// ============================================================
// Kernel 0: zero scores + attended region
// ============================================================
__global__ void zero_kernel(float* __restrict__ outAtt){
    int i = blockIdx.x * 256 + threadIdx.x;
    g_scores[i] = 0.f;
    if (i < B*H) outAtt[i] = 0.f;
}

// ============================================================
// Staging: fp32 -> fp16 swizzled SW128 tile images (128B rows)
// ============================================================
__global__ void stageA_kernel(const float* __restrict__ past){
    int bidx = blockIdx.x;               // MT*KS2 = 8192 blocks, 256 thr
    int ks = bidx & 15;
    int mt = bidx >> 4;
    int t = threadIdx.x;
    int row = t >> 1;                    // 0..127
    int hoff = (t & 1) * 32;             // halves
    const float4* src = reinterpret_cast<const float4*>(
        &past[(size_t)(mt*BM + row)*H + ks*BK + hoff]);
    __half hbuf[32];
    #pragma unroll
    for (int i = 0; i < 8; i++){
        float4 v = src[i];
        hbuf[i*4+0] = __float2half_rn(v.x); hbuf[i*4+1] = __float2half_rn(v.y);
        hbuf[i*4+2] = __float2half_rn(v.z); hbuf[i*4+3] = __float2half_rn(v.w);
    }
    char* tileBase = reinterpret_cast<char*>(
        &g_Ah[(size_t)(mt*KS2 + ks)*A_TILE_HALFS]);
    const uint4* hb = reinterpret_cast<const uint4*>(hbuf);
    uint32_t off0 = (uint32_t)(row*128 + hoff*2);
    #pragma unroll
    for (int j = 0; j < 4; j++){
        uint32_t off = off0 + j*16;
        *reinterpret_cast<uint4*>(tileBase + SW128(off)) = hb[j];
    }
}

__global__ void stageB_kernel(const float* __restrict__ Wproj){
    int bidx = blockIdx.x;               // NT*KS2 = 64 blocks, 512 thr
    int ks = bidx & 15;
    int nt = bidx >> 4;
    int t = threadIdx.x;
    int row = t >> 1;                    // 0..255
    int hoff = (t & 1) * 32;
    const float4* src = reinterpret_cast<const float4*>(
        &Wproj[(size_t)(nt*BN + row)*2048 + ks*BK + hoff]);
    __half hbuf[32];
    #pragma unroll
    for (int i = 0; i < 8; i++){
        float4 v = src[i];
        hbuf[i*4+0] = __float2half_rn(v.x); hbuf[i*4+1] = __float2half_rn(v.y);
        hbuf[i*4+2] = __float2half_rn(v.z); hbuf[i*4+3] = __float2half_rn(v.w);
    }
    char* tileBase = reinterpret_cast<char*>(
        &g_Bh[(size_t)(nt*KS2 + ks)*B_TILE_HALFS]);
    const uint4* hb = reinterpret_cast<const uint4*>(hbuf);
    uint32_t off0 = (uint32_t)(row*128 + hoff*2);
    #pragma unroll
    for (int j = 0; j < 4; j++){
        uint32_t off = off0 + j*16;
        *reinterpret_cast<uint4*>(tileBase + SW128(off)) = hb[j];
    }
}

// ============================================================
// Kernel 1: cbias[b,h] = current[b,:] . Wc[h,:] + b_proj[h]
// ============================================================
__global__ void cbias_kernel(const float* __restrict__ current,
                             const float* __restrict__ Wproj,
                             const float* __restrict__ bproj){
    int lane = threadIdx.x & 31, w = threadIdx.x >> 5;
    int h = blockIdx.x * 8 + w;
    int b = blockIdx.y;
    const float4* cr = reinterpret_cast<const float4*>(current + b*H);
    const float4* wr = reinterpret_cast<const float4*>(Wproj + (size_t)h*2048 + H);
    float p = 0.f;
    #pragma unroll
    for (int d = lane; d < 256; d += 32){
        float4 c = cr[d], v = wr[d];
        p += c.x*v.x + c.y*v.y + c.z*v.z + c.w*v.w;
    }
    #pragma unroll
    for (int o = 16; o; o >>= 1) p += __shfl_xor_sync(0xffffffffu, p, o);
    if (lane == 0) g_cbias[b*H + h] = p + bproj[h];
}

// ============================================================
// Kernel 2: fp16 mma.sync GEMM (swizzled ldmatrix + bulk pipeline)
//           + fused tanh/score epilogue
// ============================================================
__global__ void __launch_bounds__(256, 1) gemm_score(
    const float* __restrict__ wscore)
{
    extern __shared__ __align__(128) char dsm[];
    __shared__ uint64_t mbar[NSTAGES];
    __shared__ float cbS[BN];
    __shared__ float wsS[BN];

    const int tid = threadIdx.x, wid = tid >> 5, lane = tid & 31;
    const int ntIdx = blockIdx.x, mtIdx = blockIdx.y;
    const int mTile = mtIdx * BM;
    const int nTile = ntIdx * BN;
    const int b = mTile >> 11;
    const uint32_t smemBase = smem_u32(dsm);

    if (tid == 0){
        #pragma unroll
        for (int s = 0; s < NSTAGES; s++) MBARRIER_INIT(smem_u32(&mbar[s]), 1);
    }
    cbS[tid] = g_cbias[b*H + nTile + tid];
    wsS[tid] = wscore[nTile + tid];
    __syncthreads();

    if (tid == 0){
        #pragma unroll
        for (int s = 0; s < NSTAGES; s++){
            uint32_t mb = smem_u32(&mbar[s]);
            MBARRIER_EXPECT_TX(mb, STAGE_BYTES);
            bulk_g2s(smemBase + s*STAGE_BYTES,
                     &g_Ah[(size_t)(mtIdx*KS2 + s)*A_TILE_HALFS], A_TILE_BYTES, mb);
            bulk_g2s(smemBase + s*STAGE_BYTES + A_TILE_BYTES,
                     &g_Bh[(size_t)(ntIdx*KS2 + s)*B_TILE_HALFS], B_TILE_BYTES, mb);
        }
    }

    const int warpM = wid >> 2;           // 0..1 (64 rows)
    const int warpN = wid & 3;            // 0..3 (64 cols)
    const int qr = lane >> 2, qc = lane & 3;

    // lane-invariant pieces of the ldmatrix addresses (byte offsets in tile)
    const uint32_t aRowLane = (uint32_t)(lane & 15);          // row within 16
    const uint32_t aColLane = (uint32_t)((lane >> 4) * 16);   // byte col (0/16)
    const uint32_t bRowLane = (uint32_t)(((lane >> 4) << 3) + (lane & 7));
    const uint32_t bColLane = (uint32_t)(((lane >> 3) & 1) * 16);

    float acc[4][8][4];
    #pragma unroll
    for (int i = 0; i < 4; i++)
        #pragma unroll
        for (int j = 0; j < 8; j++)
            #pragma unroll
            for (int k = 0; k < 4; k++) acc[i][j][k] = 0.f;

    for (int s = 0; s < KS2; s++){
        int slot = s % NSTAGES;
        MBARRIER_WAIT_PARITY(smem_u32(&mbar[slot]), (s/NSTAGES)&1);

        uint32_t aBase = smemBase + slot*STAGE_BYTES;
        uint32_t bBase = aBase + A_TILE_BYTES;

        #pragma unroll
        for (int kk = 0; kk < BK; kk += 16){
            uint32_t a[4][4], bq[4][4];
            #pragma unroll
            for (int mf = 0; mf < 4; mf++){
                uint32_t off = (uint32_t)(warpM*64 + mf*16 + aRowLane)*128u
                             + (uint32_t)kk*2u + aColLane;
                ldmx4(a[mf], aBase + SW128(off));
            }
            #pragma unroll
            for (int np = 0; np < 4; np++){
                uint32_t off = (uint32_t)(warpN*64 + np*16 + bRowLane)*128u
                             + (uint32_t)kk*2u + bColLane;
                ldmx4(bq[np], bBase + SW128(off));
            }
            #pragma unroll
            for (int np = 0; np < 4; np++){
                #pragma unroll
                for (int hh = 0; hh < 2; hh++){
                    int nf = np*2 + hh;
                    #pragma unroll
                    for (int mf = 0; mf < 4; mf++)
                        mma16816(acc[mf][nf], a[mf], bq[np][hh*2], bq[np][hh*2+1]);
                }
            }
        }
        __syncthreads();
        if (tid == 0 && s + NSTAGES < KS2){
            int ns = s + NSTAGES;
            uint32_t mb = smem_u32(&mbar[slot]);
            MBARRIER_EXPECT_TX(mb, STAGE_BYTES);
            bulk_g2s(smemBase + slot*STAGE_BYTES,
                     &g_Ah[(size_t)(mtIdx*KS2 + ns)*A_TILE_HALFS], A_TILE_BYTES, mb);
            bulk_g2s(smemBase + slot*STAGE_BYTES + A_TILE_BYTES,
                     &g_Bh[(size_t)(ntIdx*KS2 + ns)*B_TILE_HALFS], B_TILE_BYTES, mb);
        }
    }

    // ---- fused epilogue: tanh + dot(w_score) per row, quad-reduce ----
    #pragma unroll
    for (int mf = 0; mf < 4; mf++){
        #pragma unroll
        for (int rr = 0; rr < 2; rr++){
            float p = 0.f;
            #pragma unroll
            for (int nf = 0; nf < 8; nf++){
                int c0 = warpN*64 + nf*8 + qc*2;
                p += tanh_fast(acc[mf][nf][rr*2+0] + cbS[c0    ]) * wsS[c0    ];
                p += tanh_fast(acc[mf][nf][rr*2+1] + cbS[c0 + 1]) * wsS[c0 + 1];
            }
            p += __shfl_xor_sync(0xffffffffu, p, 1);
            p += __shfl_xor_sync(0xffffffffu, p, 2);
            if (qc == 0){
                int r = mTile + warpM*64 + mf*16 + qr + rr*8;
                atomicAdd(&g_scores[r], p);
            }
        }
    }
}

// ============================================================
// Kernel 3: per-batch softmax over S
// ============================================================
__global__ void softmax_kernel(float* __restrict__ attn){
    __shared__ float red[256];
    int bidx = blockIdx.x, tid = threadIdx.x;
    const float* sc = g_scores + bidx*S;
    float m = -1e30f;
    for (int s = tid; s < S; s += 256) m = fmaxf(m, sc[s]);
    red[tid] = m; __syncthreads();
    for (int o = 128; o; o >>= 1){ if (tid < o) red[tid] = fmaxf(red[tid], red[tid+o]); __syncthreads(); }
    m = red[0]; __syncthreads();
    float sum = 0.f;
    float* a = attn + bidx*S;
    for (int s = tid; s < S; s += 256){ float e = __expf(sc[s] - m); a[s] = e; sum += e; }
    red[tid] = sum; __syncthreads();
    for (int o = 128; o; o >>= 1){ if (tid < o) red[tid] += red[tid+o]; __syncthreads(); }
    float inv = 1.f / red[0];
    for (int s = tid; s < S; s += 256) a[s] *= inv;
}

// ============================================================
// Kernel 4: attended[b,d] = sum_s attn[b,s] * past[b,s,d]
// ============================================================
__global__ void attend_kernel(const float* __restrict__ past,
                              const float* __restrict__ attn,
                              float* __restrict__ outAtt){
    __shared__ float w[256];
    int bidx = blockIdx.y, ch = blockIdx.x, tid = threadIdx.x;
    int s0 = ch * 256;
    w[tid] = attn[bidx*S + s0 + tid];
    __syncthreads();
    const float4* P = reinterpret_cast<const float4*>(past + (size_t)(bidx*S + s0)*H);
    float4 acc = make_float4(0.f, 0.f, 0.f, 0.f);
    #pragma unroll 4
    for (int s = 0; s < 256; s++){
        float4 v = P[(size_t)s*256 + tid];
        float ws = w[s];
        acc.x += ws*v.x; acc.y += ws*v.y; acc.z += ws*v.z; acc.w += ws*v.w;
    }
    float* o = outAtt + bidx*H + tid*4;
    atomicAdd(o+0, acc.x); atomicAdd(o+1, acc.y);
    atomicAdd(o+2, acc.z); atomicAdd(o+3, acc.w);
}

// ============================================================
extern "C" void kernel_launch(void* const* d_in, const int* in_sizes, int n_in,
                              void* d_out, int out_size)
{
    const float* current = (const float*)d_in[0];   // [32,1024]
    const float* past    = (const float*)d_in[1];   // [32,2048,1024]
    const float* Wproj   = (const float*)d_in[2];   // [1024,2048]
    const float* bproj   = (const float*)d_in[3];   // [1024]
    const float* wscore  = (const float*)d_in[4];   // [1024]

    float* outAtt  = (float*)d_out;                 // attended [32,1024]
    float* outAttn = (float*)d_out + B*H;           // attn_weights [32,2048]

    static int smem_set = 0;
    if (!smem_set){
        cudaFuncSetAttribute(gemm_score,
                             cudaFuncAttributeMaxDynamicSharedMemorySize, DSMEM_BYTES);
        smem_set = 1;
    }

    zero_kernel   <<<256, 256>>>(outAtt);
    stageA_kernel <<<MT*KS2, 256>>>(past);       // 8192 blocks
    stageB_kernel <<<NT*KS2, 512>>>(Wproj);      // 64 blocks
    cbias_kernel  <<<dim3(128, 32), 256>>>(current, Wproj, bproj);
    gemm_score    <<<dim3(NT, MT), 256, DSMEM_BYTES>>>(wscore);
    softmax_kernel<<<32, 256>>>(outAttn);
    attend_kernel <<<dim3(S/256, B), 256>>>(past, outAttn, outAtt);
}